// round 12
// baseline (speedup 1.0000x reference)
#include <cuda_runtime.h>
#include <cuda_fp16.h>
#include <cstdint>

#define D 128
#define K 32
#define GROWS 32          // rows per GEMM block
#define GW 4              // warps (nodes) per gather block
#define NMAX 50000

// Scratch (allocation-free: static __device__ globals)
__device__ __half g_msgh[NMAX * D];   // fp16 message buffer (12.8 MB)
__device__ float  g_x[NMAX * D];      // fp32 inter-layer activations

// msg[row] = fp16( mask[row] * ( (transform(x[row]) * mask[row]) @ W ) )
__global__ void __launch_bounds__(128) gemm_kernel(
    const float* __restrict__ xin, const float* __restrict__ W,
    const float* __restrict__ mask, __half* __restrict__ msgh,
    int N, int do_logmap, int from_gx)
{
    __shared__ float xs[GROWS][D];
    __shared__ float Ws[32][D];

    const float* x = from_gx ? g_x : xin;

    int tid  = threadIdx.x;          // 0..127
    int lane = tid & 31;
    int warp = tid >> 5;             // 0..3
    int row0 = blockIdx.x * GROWS;

    #pragma unroll
    for (int i = 0; i < 8; i++) {
        int lr  = warp * 8 + i;
        int row = row0 + lr;
        float4 v = make_float4(0.f, 0.f, 0.f, 0.f);
        float  m = 0.f;
        if (row < N) {
            v = __ldg((const float4*)(x + (size_t)row * D) + lane);
            m = __ldg(mask + row);
        }
        float ss = v.x * v.x + v.y * v.y + v.z * v.z + v.w * v.w;
        #pragma unroll
        for (int o = 16; o > 0; o >>= 1) ss += __shfl_xor_sync(0xffffffffu, ss, o);
        float s;
        if (do_logmap) {
            float n  = sqrtf(ss);
            float nc = fminf(fmaxf(n, 1e-5f), 1.f - 1e-5f);
            s = atanhf(nc) / fmaxf(n, 1e-5f) * m;
        } else {
            s = m;
        }
        float4 o4 = make_float4(v.x * s, v.y * s, v.z * s, v.w * s);
        *((float4*)&xs[lr][0] + lane) = o4;
    }
    __syncthreads();

    float acc[8][4];
    #pragma unroll
    for (int r = 0; r < 8; r++) {
        acc[r][0] = 0.f; acc[r][1] = 0.f; acc[r][2] = 0.f; acc[r][3] = 0.f;
    }

    for (int jc = 0; jc < 4; jc++) {
        #pragma unroll
        for (int t = 0; t < 8; t++) {
            int idx = tid + t * 128;            // 0..1023
            int jr  = idx >> 5;
            int c4  = idx & 31;
            ((float4*)&Ws[jr][0])[c4] = __ldg((const float4*)(W + (size_t)(jc * 32 + jr) * D) + c4);
        }
        __syncthreads();

        #pragma unroll
        for (int j = 0; j < 32; j++) {
            float4 wv = *((float4*)&Ws[j][0] + lane);
            #pragma unroll
            for (int r = 0; r < 8; r++) {
                float xb = xs[warp * 8 + r][jc * 32 + j];
                acc[r][0] += xb * wv.x;
                acc[r][1] += xb * wv.y;
                acc[r][2] += xb * wv.z;
                acc[r][3] += xb * wv.w;
            }
        }
        __syncthreads();
    }

    #pragma unroll
    for (int r = 0; r < 8; r++) {
        int row = row0 + warp * 8 + r;
        if (row < N) {
            float m = __ldg(mask + row);
            __half2 h01 = __floats2half2_rn(acc[r][0] * m, acc[r][1] * m);
            __half2 h23 = __floats2half2_rn(acc[r][2] * m, acc[r][3] * m);
            uint2 pk;
            pk.x = *(unsigned int*)&h01;
            pk.y = *(unsigned int*)&h23;
            *((uint2*)(msgh + (size_t)row * D) + lane) = pk;
        }
    }
}

// out[n] = relu( expmap( mask[n] * sum_k w[n,k] * msg[adj[n,k]] ) * mask[n] ) * mask[n]
// One warp per node. All 32 neighbor rows fetched with cp.async into SMEM:
// no destination registers -> ptxas cannot re-serialize -> true MLP=32/warp.
__global__ void __launch_bounds__(128) gather_kernel(
    const __half* __restrict__ msgh, const int* __restrict__ adj,
    const float* __restrict__ wgt, const float* __restrict__ mask,
    float* __restrict__ outp, int N, int to_gx)
{
    // [warp][neighbor k][lane] : 8 B per lane, 256 B per row, 8 KB per warp, 32 KB total
    __shared__ __align__(16) uint2 sm[GW][K][32];

    float* out = to_gx ? g_x : outp;
    int wib  = threadIdx.x >> 5;     // warp in block
    int lane = threadIdx.x & 31;
    int n    = blockIdx.x * GW + wib;
    if (n >= N) return;

    int   a  = __ldg(adj + (size_t)n * K + lane);   // neighbor id held by lane k
    float wk = __ldg(wgt + (size_t)n * K + lane);

    // issue 32 independent 8-byte async copies (this lane's slice of each row)
    unsigned sdst0 = (unsigned)__cvta_generic_to_shared(&sm[wib][0][lane]);
    const char* gbase = (const char*)msgh;
    #pragma unroll
    for (int k = 0; k < K; k++) {
        int row = __shfl_sync(0xffffffffu, a, k);
        const void* gsrc = gbase + (size_t)row * (D * 2) + lane * 8;
        unsigned sdst = sdst0 + k * 256;
        asm volatile("cp.async.ca.shared.global [%0], [%1], 8;" :: "r"(sdst), "l"(gsrc));
    }
    asm volatile("cp.async.commit_group;");
    asm volatile("cp.async.wait_group 0;");

    // accumulate from SMEM (each lane consumes exactly the bytes it fetched)
    float4 acc0 = make_float4(0.f, 0.f, 0.f, 0.f);
    float4 acc1 = make_float4(0.f, 0.f, 0.f, 0.f);
    #pragma unroll
    for (int k = 0; k < K; k += 2) {
        float w0 = __shfl_sync(0xffffffffu, wk, k);
        float w1 = __shfl_sync(0xffffffffu, wk, k + 1);
        uint2 v0 = sm[wib][k][lane];
        uint2 v1 = sm[wib][k + 1][lane];
        float2 a01 = __half22float2(*(const __half2*)&v0.x);
        float2 a23 = __half22float2(*(const __half2*)&v0.y);
        float2 b01 = __half22float2(*(const __half2*)&v1.x);
        float2 b23 = __half22float2(*(const __half2*)&v1.y);
        acc0.x += w0 * a01.x; acc0.y += w0 * a01.y;
        acc0.z += w0 * a23.x; acc0.w += w0 * a23.y;
        acc1.x += w1 * b01.x; acc1.y += w1 * b01.y;
        acc1.z += w1 * b23.x; acc1.w += w1 * b23.y;
    }

    float4 acc;
    acc.x = acc0.x + acc1.x;
    acc.y = acc0.y + acc1.y;
    acc.z = acc0.z + acc1.z;
    acc.w = acc0.w + acc1.w;

    float m = __ldg(mask + n);
    acc.x *= m; acc.y *= m; acc.z *= m; acc.w *= m;   // combined = sum * mask

    float ss = acc.x * acc.x + acc.y * acc.y + acc.z * acc.z + acc.w * acc.w;
    #pragma unroll
    for (int o = 16; o > 0; o >>= 1) ss += __shfl_xor_sync(0xffffffffu, ss, o);

    float nn = sqrtf(ss);
    float nc = fminf(fmaxf(nn, 1e-5f), 15.f);
    float s  = tanhf(nc) / fmaxf(nn, 1e-5f);          // expmap scale

    float4 o4;
    o4.x = fmaxf(acc.x * s * m, 0.f) * m;
    o4.y = fmaxf(acc.y * s * m, 0.f) * m;
    o4.z = fmaxf(acc.z * s * m, 0.f) * m;
    o4.w = fmaxf(acc.w * s * m, 0.f) * m;
    *((float4*)(out + (size_t)n * D) + lane) = o4;
}

extern "C" void kernel_launch(void* const* d_in, const int* in_sizes, int n_in,
                              void* d_out, int out_size) {
    const float* node_repr = (const float*)d_in[0];
    const int*   adj       = (const int*)d_in[1];
    const float* wgt       = (const float*)d_in[2];
    const float* mask      = (const float*)d_in[3];
    const float* mw        = (const float*)d_in[4];   // [2,128,128]
    float* out = (float*)d_out;

    int N = in_sizes[0] / D;

    dim3 gemm_grid((N + GROWS - 1) / GROWS);
    dim3 gath_grid((N + GW - 1) / GW);   // 4 warps/block, 1 warp per node

    // layer 0
    gemm_kernel<<<gemm_grid, 128>>>(node_repr, mw, mask, g_msgh, N, /*logmap=*/0, /*from_gx=*/0);
    gather_kernel<<<gath_grid, 128>>>(g_msgh, adj, wgt, mask, out, N, /*to_gx=*/1);
    // layer 1
    gemm_kernel<<<gemm_grid, 128>>>(nullptr, mw + D * D, mask, g_msgh, N, /*logmap=*/1, /*from_gx=*/1);
    gather_kernel<<<gath_grid, 128>>>(g_msgh, adj, wgt, mask, out, N, /*to_gx=*/0);
}

// round 16
// speedup vs baseline: 26.5891x; 26.5891x over previous
#include <cuda_runtime.h>
#include <cuda_fp16.h>
#include <cstdint>

#define D     128
#define K     32
#define TILE  32          // nodes per block
#define NMAX  50000

// Final-output staging. Deliberately the ONLY bulk traffic through a __device__
// global (theory: module globals may be host-resident on GB300 -> ~200 GB/s).
__device__ float g_scr[NMAX * D];

// Fused layer kernel (linearity reorder: gather FIRST, then dense @W):
//   combined[n] = mask[n] * sum_k w[n,k] * s_a * src[adj[n,k]]
//     layer1: src = node_repr (f32 rows), s_a = mask_a^2
//     layer2: src = d_out as fp16 rows (stores logmap(x1)*mask), s_a = mask_a
//   vals = combined @ W
//   layer1: x1 = relu(expmap(vals)*m)*m ; store fp16( logmap(x1)*m ) -> outh (d_out)
//   layer2: store relu(expmap(vals)*m)*m -> outf (g_scr)
__global__ void __launch_bounds__(256) layer_kernel(
    const float* __restrict__ srcf, const __half* __restrict__ srch,
    const int* __restrict__ adj, const float* __restrict__ wgt,
    const float* __restrict__ mask, const float* __restrict__ W,
    __half* __restrict__ outh, float* __restrict__ outf,
    int N, int is_layer2)
{
    __shared__ float xs[TILE][D];   // combined tile (16 KB)
    __shared__ float Ws[32][D];     // W staging (16 KB)

    int tid  = threadIdx.x;          // 0..255
    int lane = tid & 31;
    int warp = tid >> 5;             // 0..7
    int row0 = blockIdx.x * TILE;

    // ---------- Phase 1: gather + weighted combine (warp w -> nodes w*4..w*4+3) ----------
    #pragma unroll
    for (int i = 0; i < 4; i++) {
        int node = warp * 4 + i;
        int n    = row0 + node;
        float4 acc = make_float4(0.f, 0.f, 0.f, 0.f);

        if (n < N) {
            int   a  = __ldg(adj + (size_t)n * K + lane);     // this lane's neighbor
            float wk = __ldg(wgt + (size_t)n * K + lane);
            float ma = __ldg(mask + a);
            float sk = is_layer2 ? (wk * ma) : (wk * ma * ma); // per-neighbor scalar

            if (!is_layer2) {
                // f32 rows, 512 B: lane reads its float4 slice
                #pragma unroll
                for (int k = 0; k < K; k += 8) {
                    int r0 = __shfl_sync(0xffffffffu, a, k + 0);
                    int r1 = __shfl_sync(0xffffffffu, a, k + 1);
                    int r2 = __shfl_sync(0xffffffffu, a, k + 2);
                    int r3 = __shfl_sync(0xffffffffu, a, k + 3);
                    int r4 = __shfl_sync(0xffffffffu, a, k + 4);
                    int r5 = __shfl_sync(0xffffffffu, a, k + 5);
                    int r6 = __shfl_sync(0xffffffffu, a, k + 6);
                    int r7 = __shfl_sync(0xffffffffu, a, k + 7);
                    const float4* mp = (const float4*)srcf;
                    float4 v0 = __ldg(mp + (size_t)r0 * (D/4) + lane);
                    float4 v1 = __ldg(mp + (size_t)r1 * (D/4) + lane);
                    float4 v2 = __ldg(mp + (size_t)r2 * (D/4) + lane);
                    float4 v3 = __ldg(mp + (size_t)r3 * (D/4) + lane);
                    float4 v4 = __ldg(mp + (size_t)r4 * (D/4) + lane);
                    float4 v5 = __ldg(mp + (size_t)r5 * (D/4) + lane);
                    float4 v6 = __ldg(mp + (size_t)r6 * (D/4) + lane);
                    float4 v7 = __ldg(mp + (size_t)r7 * (D/4) + lane);
                    float s0 = __shfl_sync(0xffffffffu, sk, k + 0);
                    float s1 = __shfl_sync(0xffffffffu, sk, k + 1);
                    float s2 = __shfl_sync(0xffffffffu, sk, k + 2);
                    float s3 = __shfl_sync(0xffffffffu, sk, k + 3);
                    float s4 = __shfl_sync(0xffffffffu, sk, k + 4);
                    float s5 = __shfl_sync(0xffffffffu, sk, k + 5);
                    float s6 = __shfl_sync(0xffffffffu, sk, k + 6);
                    float s7 = __shfl_sync(0xffffffffu, sk, k + 7);
                    acc.x += s0*v0.x + s1*v1.x + s2*v2.x + s3*v3.x
                           + s4*v4.x + s5*v5.x + s6*v6.x + s7*v7.x;
                    acc.y += s0*v0.y + s1*v1.y + s2*v2.y + s3*v3.y
                           + s4*v4.y + s5*v5.y + s6*v6.y + s7*v7.y;
                    acc.z += s0*v0.z + s1*v1.z + s2*v2.z + s3*v3.z
                           + s4*v4.z + s5*v5.z + s6*v6.z + s7*v7.z;
                    acc.w += s0*v0.w + s1*v1.w + s2*v2.w + s3*v3.w
                           + s4*v4.w + s5*v5.w + s6*v6.w + s7*v7.w;
                }
            } else {
                // fp16 rows, 256 B: lane reads its uint2 (4 halves)
                const uint2* mp = (const uint2*)srch;
                #pragma unroll
                for (int k = 0; k < K; k += 8) {
                    int r0 = __shfl_sync(0xffffffffu, a, k + 0);
                    int r1 = __shfl_sync(0xffffffffu, a, k + 1);
                    int r2 = __shfl_sync(0xffffffffu, a, k + 2);
                    int r3 = __shfl_sync(0xffffffffu, a, k + 3);
                    int r4 = __shfl_sync(0xffffffffu, a, k + 4);
                    int r5 = __shfl_sync(0xffffffffu, a, k + 5);
                    int r6 = __shfl_sync(0xffffffffu, a, k + 6);
                    int r7 = __shfl_sync(0xffffffffu, a, k + 7);
                    uint2 v0 = __ldg(mp + (size_t)r0 * (D/4) + lane);
                    uint2 v1 = __ldg(mp + (size_t)r1 * (D/4) + lane);
                    uint2 v2 = __ldg(mp + (size_t)r2 * (D/4) + lane);
                    uint2 v3 = __ldg(mp + (size_t)r3 * (D/4) + lane);
                    uint2 v4 = __ldg(mp + (size_t)r4 * (D/4) + lane);
                    uint2 v5 = __ldg(mp + (size_t)r5 * (D/4) + lane);
                    uint2 v6 = __ldg(mp + (size_t)r6 * (D/4) + lane);
                    uint2 v7 = __ldg(mp + (size_t)r7 * (D/4) + lane);
                    float s0 = __shfl_sync(0xffffffffu, sk, k + 0);
                    float s1 = __shfl_sync(0xffffffffu, sk, k + 1);
                    float s2 = __shfl_sync(0xffffffffu, sk, k + 2);
                    float s3 = __shfl_sync(0xffffffffu, sk, k + 3);
                    float s4 = __shfl_sync(0xffffffffu, sk, k + 4);
                    float s5 = __shfl_sync(0xffffffffu, sk, k + 5);
                    float s6 = __shfl_sync(0xffffffffu, sk, k + 6);
                    float s7 = __shfl_sync(0xffffffffu, sk, k + 7);
                    #define ACCH(V, S)                                         \
                    {                                                          \
                        float2 f01 = __half22float2(*(const __half2*)&V.x);    \
                        float2 f23 = __half22float2(*(const __half2*)&V.y);    \
                        acc.x += (S) * f01.x; acc.y += (S) * f01.y;            \
                        acc.z += (S) * f23.x; acc.w += (S) * f23.y;            \
                    }
                    ACCH(v0, s0) ACCH(v1, s1) ACCH(v2, s2) ACCH(v3, s3)
                    ACCH(v4, s4) ACCH(v5, s5) ACCH(v6, s6) ACCH(v7, s7)
                    #undef ACCH
                }
            }
            float mn = __ldg(mask + n);       // combined *= mask_n
            acc.x *= mn; acc.y *= mn; acc.z *= mn; acc.w *= mn;
        }
        *((float4*)&xs[node][0] + lane) = acc;   // zeros for n>=N
    }
    __syncthreads();

    // ---------- Phase 2: tile GEMM  (warp -> 4 rows, lane -> 4 cols) ----------
    float vac[4][4];
    #pragma unroll
    for (int r = 0; r < 4; r++) { vac[r][0]=0.f; vac[r][1]=0.f; vac[r][2]=0.f; vac[r][3]=0.f; }

    for (int jc = 0; jc < 4; jc++) {
        #pragma unroll
        for (int t = 0; t < 4; t++) {
            int idx = tid + t * 256;              // 0..1023
            int jr  = idx >> 5;
            int c4  = idx & 31;
            ((float4*)&Ws[jr][0])[c4] = __ldg((const float4*)(W + (size_t)(jc*32 + jr) * D) + c4);
        }
        __syncthreads();

        #pragma unroll
        for (int j = 0; j < 32; j++) {
            float4 wv = *((float4*)&Ws[j][0] + lane);
            #pragma unroll
            for (int r = 0; r < 4; r++) {
                float xb = xs[warp * 4 + r][jc * 32 + j];
                vac[r][0] += xb * wv.x;
                vac[r][1] += xb * wv.y;
                vac[r][2] += xb * wv.z;
                vac[r][3] += xb * wv.w;
            }
        }
        __syncthreads();
    }

    // ---------- Phase 3: epilogue (maps + store) ----------
    #pragma unroll
    for (int r = 0; r < 4; r++) {
        int row = row0 + warp * 4 + r;
        if (row >= N) continue;
        float m = __ldg(mask + row);
        float v0 = vac[r][0], v1 = vac[r][1], v2 = vac[r][2], v3 = vac[r][3];

        // expmap scale
        float ss = v0*v0 + v1*v1 + v2*v2 + v3*v3;
        #pragma unroll
        for (int o = 16; o > 0; o >>= 1) ss += __shfl_xor_sync(0xffffffffu, ss, o);
        float n1  = sqrtf(ss);
        float nc1 = fminf(fmaxf(n1, 1e-5f), 15.f);
        float se  = tanhf(nc1) / fmaxf(n1, 1e-5f);

        // x1 = relu(expmap * m) * m
        float x0 = fmaxf(v0 * se * m, 0.f) * m;
        float x1 = fmaxf(v1 * se * m, 0.f) * m;
        float x2 = fmaxf(v2 * se * m, 0.f) * m;
        float x3 = fmaxf(v3 * se * m, 0.f) * m;

        if (!is_layer2) {
            // z = logmap(x1) * m, stored fp16
            float ss2 = x0*x0 + x1*x1 + x2*x2 + x3*x3;
            #pragma unroll
            for (int o = 16; o > 0; o >>= 1) ss2 += __shfl_xor_sync(0xffffffffu, ss2, o);
            float n2  = sqrtf(ss2);
            float nc2 = fminf(fmaxf(n2, 1e-5f), 1.f - 1e-5f);
            float sl  = atanhf(nc2) / fmaxf(n2, 1e-5f) * m;
            __half2 h01 = __floats2half2_rn(x0 * sl, x1 * sl);
            __half2 h23 = __floats2half2_rn(x2 * sl, x3 * sl);
            uint2 pk;
            pk.x = *(unsigned int*)&h01;
            pk.y = *(unsigned int*)&h23;
            *((uint2*)(outh + (size_t)row * D) + lane) = pk;
        } else {
            float4 o4 = make_float4(x0, x1, x2, x3);
            *((float4*)(outf + (size_t)row * D) + lane) = o4;
        }
    }
}

// Simple staging copy: g_scr -> d_out (f32), grid-strided float4.
__global__ void __launch_bounds__(256) copy_kernel(
    const float* __restrict__ src, float* __restrict__ dst, int n4)
{
    int i = blockIdx.x * blockDim.x + threadIdx.x;
    int stride = gridDim.x * blockDim.x;
    const float4* s = (const float4*)src;
    float4* d = (float4*)dst;
    for (; i < n4; i += stride) d[i] = s[i];
}

extern "C" void kernel_launch(void* const* d_in, const int* in_sizes, int n_in,
                              void* d_out, int out_size) {
    const float* node_repr = (const float*)d_in[0];
    const int*   adj       = (const int*)d_in[1];
    const float* wgt       = (const float*)d_in[2];
    const float* mask      = (const float*)d_in[3];
    const float* mw        = (const float*)d_in[4];   // [2,128,128]
    float* out = (float*)d_out;

    int N = in_sizes[0] / D;
    dim3 grid((N + TILE - 1) / TILE);

    float* scr = nullptr;
    cudaGetSymbolAddress((void**)&scr, g_scr);

    // Layer 1: gather node_repr (input) -> @W1 -> maps -> fp16 features into d_out
    layer_kernel<<<grid, 256>>>(node_repr, nullptr, adj, wgt, mask, mw,
                                (__half*)d_out, nullptr, N, /*is_layer2=*/0);
    // Layer 2: gather fp16 features (d_out) -> @W2 -> maps -> f32 into g_scr
    layer_kernel<<<grid, 256>>>(nullptr, (const __half*)d_out, adj, wgt, mask, mw + D * D,
                                nullptr, scr, N, /*is_layer2=*/1);
    // Final: stage back into d_out with a copy kernel (graph-safe, no memcpy node)
    int n4 = (N * D) / 4;
    copy_kernel<<<592, 256>>>(scr, out, n4);
}